// round 11
// baseline (speedup 1.0000x reference)
#include <cuda_runtime.h>
#include <cuda_fp16.h>
#include <math.h>
#include <stdint.h>

// ---------------- problem constants ----------------
#define BB   4
#define SS   2048
#define DD   768
#define HH   12
#define HDIM 64
#define FF   3072
#define NTOK 8192
#define BH   48

#define SCALEQ 0.18033688011112042f   // 0.125 * log2(e)

// ---------------- fp16 scratch ----------------
#define N_H     6291456L
#define N_WQKV  1769472L
#define N_QKV1  6291456L
#define N_OC    6291456L
#define N_WO    589824L
#define N_H2    6291456L
#define N_W1    2359296L
#define N_F     25165824L
#define N_W2    2359296L

#define HO_H     0L
#define HO_WQKV  (HO_H    + N_H)
#define HO_Q     (HO_WQKV + N_WQKV)
#define HO_K     (HO_Q    + N_QKV1)
#define HO_V     (HO_K    + N_QKV1)
#define HO_OC    (HO_V    + N_QKV1)
#define HO_WO    (HO_OC   + N_OC)
#define HO_H2    (HO_WO   + N_WO)
#define HO_W1    (HO_H2   + N_H2)
#define HO_F     (HO_W1   + N_W1)
#define HO_W2    (HO_F    + N_F)
#define H_TOTAL  (HO_W2   + N_W2)

#define FO_A      0L
#define FO_BQKV   6291456L
#define F_TOTAL   (FO_BQKV + 2304L)

__device__ __align__(16) __half h_scratch[H_TOTAL];
__device__ __align__(16) float  f_scratch[F_TOTAL];

// ---------------- small helpers ----------------
__device__ __forceinline__ uint32_t pack2h(float x, float y) {
    __half2 h = __floats2half2_rn(x, y);
    return *(uint32_t*)&h;
}

__device__ __forceinline__ float ex2(float x) {
    float r;
    asm("ex2.approx.ftz.f32 %0, %1;" : "=f"(r) : "f"(x));
    return r;
}

__device__ __forceinline__ float gelu_exact(float x) {
    return 0.5f * x * (1.0f + erff(x * 0.70710678118654752f));
}

__device__ __forceinline__ void cpasync16(uint32_t dst, const void* src) {
    asm volatile("cp.async.cg.shared.global [%0], [%1], 16;\n" :: "r"(dst), "l"(src));
}
__device__ __forceinline__ void cp_commit() {
    asm volatile("cp.async.commit_group;\n");
}
template<int N> __device__ __forceinline__ void cp_wait() {
    asm volatile("cp.async.wait_group %0;\n" :: "n"(N));
}
__device__ __forceinline__ void ldm_x4(uint32_t* r, uint32_t addr) {
    asm volatile("ldmatrix.sync.aligned.m8n8.x4.shared.b16 {%0,%1,%2,%3}, [%4];\n"
                 : "=r"(r[0]), "=r"(r[1]), "=r"(r[2]), "=r"(r[3]) : "r"(addr));
}
__device__ __forceinline__ void mma16816(float* d, const uint32_t* a, const uint32_t* b) {
    asm volatile("mma.sync.aligned.m16n8k16.row.col.f32.f16.f16.f32 "
                 "{%0,%1,%2,%3},{%4,%5,%6,%7},{%8,%9},{%0,%1,%2,%3};\n"
                 : "+f"(d[0]), "+f"(d[1]), "+f"(d[2]), "+f"(d[3])
                 : "r"(a[0]), "r"(a[1]), "r"(a[2]), "r"(a[3]), "r"(b[0]), "r"(b[1]));
}

// ---------------- packing / conversion kernels ----------------
__global__ void pack_wqkv(const float* __restrict__ Wq, const float* __restrict__ Wk,
                          const float* __restrict__ Wv, const float* __restrict__ bq,
                          const float* __restrict__ bk, const float* __restrict__ bv) {
    long idx = (long)blockIdx.x * blockDim.x + threadIdx.x;
    if (idx < 2304L * 768) {
        int n = (int)(idx / 768), k = (int)(idx % 768);
        int which = n / DD;
        int r = n - which * DD;
        int h = r >> 6, e = r & 63;
        const float* W = (which == 0) ? Wq : (which == 1) ? Wk : Wv;
        h_scratch[HO_WQKV + idx] =
            __float2half(W[(long)h * (DD * HDIM) + (long)k * HDIM + e]);
    }
    if (idx < 3 * DD) {
        int which = (int)(idx / DD), r = (int)(idx % DD);
        const float* b = (which == 0) ? bq : (which == 1) ? bk : bv;
        f_scratch[FO_BQKV + idx] = b[r];
    }
}

// tiled transpose: out[n*K + k] = W[k*N + n]
__global__ void transpose_w(const float* __restrict__ W, int K, int N, long outOff) {
    __shared__ float t[32][33];
    int bx = blockIdx.x * 32, by = blockIdx.y * 32;
    int tx = threadIdx.x, ty = threadIdx.y;  // block (32,8)
    #pragma unroll
    for (int j = 0; j < 32; j += 8)
        t[ty + j][tx] = W[(long)(by + ty + j) * N + bx + tx];
    __syncthreads();
    __half* o = h_scratch + outOff;
    #pragma unroll
    for (int j = 0; j < 32; j += 8)
        o[(long)(bx + ty + j) * K + by + tx] = __float2half(t[tx][ty + j]);
}

// LayerNorm over rows of 768, output fp16
__global__ void ln_fp16(const float* __restrict__ xext, int useScratch,
                        const float* __restrict__ g, const float* __restrict__ b,
                        long outOff) {
    const float* src = (useScratch ? (const float*)(f_scratch + FO_A) : xext)
                       + (long)blockIdx.x * DD;
    int tid = threadIdx.x;
    float s = 0.f, s2 = 0.f;
    for (int i = tid; i < DD; i += 256) { float v = src[i]; s += v; s2 += v * v; }
    #pragma unroll
    for (int off = 16; off; off >>= 1) {
        s  += __shfl_down_sync(0xffffffffu, s,  off);
        s2 += __shfl_down_sync(0xffffffffu, s2, off);
    }
    __shared__ float sh[2][8];
    int wid = tid >> 5, lane = tid & 31;
    if (lane == 0) { sh[0][wid] = s; sh[1][wid] = s2; }
    __syncthreads();
    if (tid == 0) {
        float ts = 0.f, ts2 = 0.f;
        #pragma unroll
        for (int i = 0; i < 8; i++) { ts += sh[0][i]; ts2 += sh[1][i]; }
        float mean = ts * (1.0f / DD);
        float var = ts2 * (1.0f / DD) - mean * mean;
        sh[0][0] = mean;
        sh[1][0] = rsqrtf(var + 1e-5f);
    }
    __syncthreads();
    float mean = sh[0][0], rstd = sh[1][0];
    long base = outOff + (long)blockIdx.x * DD;
    for (int i = tid; i < DD; i += 256) {
        float v = (src[i] - mean) * rstd * g[i] + b[i];
        h_scratch[base + i] = __float2half(v);
    }
}

// ---------------- fp16 tensor-core GEMM (3-stage pipeline) ----------------
// A: [M,K] K-major fp16.  B: [N,K] K-major fp16.
// MODE 0: fp32 out (+bias).  MODE 1: QKV scatter (+bias, Q scaled).  MODE 3: gelu -> f fp16
template<int BM, int BN, int BK, int WM, int WN, int MODE>
__global__ void __launch_bounds__(256, 2)
mma_gemm(const __half* __restrict__ A, const __half* __restrict__ B,
         const float* __restrict__ bias, float* __restrict__ Cf,
         int M, int N, int K, int lda, int ldb, int ldc) {
    constexpr int BKP = BK + 8;
    constexpr int WTM = BM / WM, WTN = BN / WN;
    constexpr int MF = WTM / 16, NF = WTN / 8;
    constexpr int STAGE = (BM + BN) * BKP;     // halfs per stage

    extern __shared__ __half smem[];
    const int tid = threadIdx.x, lane = tid & 31, warp = tid >> 5;
    const int wm = warp % WM, wn = warp / WM;
    const int m0 = blockIdx.y * BM, n0 = blockIdx.x * BN;

    uint32_t sbase = (uint32_t)__cvta_generic_to_shared(smem);

    auto load_stage = [&](int s, int k0) {
        uint32_t base = sbase + (uint32_t)(s * STAGE) * 2;
        #pragma unroll 2
        for (int i = tid; i < BM * (BK / 8); i += 256) {
            int row = i / (BK / 8), c = i % (BK / 8);
            cpasync16(base + (uint32_t)(row * BKP + c * 8) * 2,
                      A + (long)(m0 + row) * lda + k0 + c * 8);
        }
        #pragma unroll 2
        for (int i = tid; i < BN * (BK / 8); i += 256) {
            int row = i / (BK / 8), c = i % (BK / 8);
            cpasync16(base + (uint32_t)(BM * BKP + row * BKP + c * 8) * 2,
                      B + (long)(n0 + row) * ldb + k0 + c * 8);
        }
    };

    float acc[MF][NF][4];
    #pragma unroll
    for (int i = 0; i < MF; i++)
        #pragma unroll
        for (int j = 0; j < NF; j++)
            #pragma unroll
            for (int q = 0; q < 4; q++) acc[i][j][q] = 0.f;

    const int nIter = K / BK;
    load_stage(0, 0); cp_commit();
    load_stage(1, BK); cp_commit();

    int s = 0;
    for (int it = 0; it < nIter; ++it) {
        if (it + 1 < nIter) cp_wait<1>(); else cp_wait<0>();
        __syncthreads();
        if (it + 2 < nIter) {
            int s2 = s + 2; if (s2 >= 3) s2 -= 3;
            load_stage(s2, (it + 2) * BK);
            cp_commit();
        }

        uint32_t base = sbase + (uint32_t)(s * STAGE) * 2;
        #pragma unroll
        for (int kk = 0; kk < BK; kk += 16) {
            uint32_t af[MF][4], bf[NF][2];
            #pragma unroll
            for (int mf = 0; mf < MF; mf++) {
                int r = wm * WTM + mf * 16 + (lane & 15);
                ldm_x4(af[mf], base + (uint32_t)(r * BKP + kk + (lane >> 4) * 8) * 2);
            }
            #pragma unroll
            for (int nf2 = 0; nf2 < NF / 2; nf2++) {
                int r = wn * WTN + nf2 * 16 + (lane & 15);
                uint32_t t[4];
                ldm_x4(t, base + (uint32_t)(BM * BKP + r * BKP + kk + (lane >> 4) * 8) * 2);
                bf[2 * nf2][0] = t[0]; bf[2 * nf2][1] = t[2];
                bf[2 * nf2 + 1][0] = t[1]; bf[2 * nf2 + 1][1] = t[3];
            }
            #pragma unroll
            for (int mf = 0; mf < MF; mf++)
                #pragma unroll
                for (int nf = 0; nf < NF; nf++)
                    mma16816(acc[mf][nf], af[mf], bf[nf]);
        }
        if (++s >= 3) s -= 3;
    }

    const int tg = lane >> 2, tp = lane & 3;
    #pragma unroll
    for (int mf = 0; mf < MF; mf++) {
        #pragma unroll
        for (int nf = 0; nf < NF; nf++) {
            int mA = m0 + wm * WTM + mf * 16 + tg;
            int nA = n0 + wn * WTN + nf * 8 + tp * 2;
            float v0 = acc[mf][nf][0], v1 = acc[mf][nf][1];
            float v2 = acc[mf][nf][2], v3 = acc[mf][nf][3];
            if (bias) {
                float b0 = bias[nA], b1 = bias[nA + 1];
                v0 += b0; v1 += b1; v2 += b0; v3 += b1;
            }
            if (MODE == 0) {
                *(float2*)&Cf[(long)mA * ldc + nA] = make_float2(v0, v1);
                *(float2*)&Cf[(long)(mA + 8) * ldc + nA] = make_float2(v2, v3);
            } else if (MODE == 1) {
                int which = nA / DD;
                int r = nA - which * DD;
                int h = r >> 6, e = r & 63;
                if (which == 2) {
                    // V transposed: strided scalar stores
                    #pragma unroll
                    for (int q = 0; q < 4; q++) {
                        int m = mA + (q >> 1) * 8;
                        int eq = e + (q & 1);
                        float v = (q == 0) ? v0 : (q == 1) ? v1 : (q == 2) ? v2 : v3;
                        int bh = (m >> 11) * HH + h;
                        h_scratch[HO_V + ((long)bh * HDIM + eq) * SS + (m & 2047)] =
                            __float2half(v);
                    }
                } else {
                    float scl = (which == 0) ? SCALEQ : 1.0f;
                    long off = (which == 0) ? HO_Q : HO_K;
                    int bh0 = (mA >> 11) * HH + h;
                    long i0 = ((long)bh0 * SS + (mA & 2047)) * HDIM + e;
                    *(uint32_t*)&h_scratch[off + i0] = pack2h(v0 * scl, v1 * scl);
                    int m8 = mA + 8;
                    int bh1 = (m8 >> 11) * HH + h;
                    long i1 = ((long)bh1 * SS + (m8 & 2047)) * HDIM + e;
                    *(uint32_t*)&h_scratch[off + i1] = pack2h(v2 * scl, v3 * scl);
                }
            } else { // MODE 3: gelu -> f (packed u32 stores)
                *(uint32_t*)&h_scratch[HO_F + (long)mA * FF + nA] =
                    pack2h(gelu_exact(v0), gelu_exact(v1));
                *(uint32_t*)&h_scratch[HO_F + (long)(mA + 8) * FF + nA] =
                    pack2h(gelu_exact(v2), gelu_exact(v3));
            }
        }
    }
}

// ---------------- flash attention (fp16, 3-stage cp.async ring) ----------------
#define KSTR 72
#define VSTR 136
#define KBYTES (128 * KSTR * 2)           // 18432
#define VBYTES (64 * VSTR * 2)            // 17408
#define FA_STAGE (KBYTES + VBYTES)        // 35840
#define FA_SMEM  (3 * FA_STAGE)           // 107520

__global__ void __launch_bounds__(256, 1)
flash_attn() {
    extern __shared__ char fsm[];
    uint32_t sbase = (uint32_t)__cvta_generic_to_shared(fsm);
    const int tid = threadIdx.x, lane = tid & 31, warp = tid >> 5;
    const int tg = lane >> 2, tp = lane & 3;
    const int m0 = blockIdx.x * 128;
    const int bh = blockIdx.y;

    const __half* Q = h_scratch + HO_Q;
    const __half* Kp = h_scratch + HO_K;
    const __half* Vp = h_scratch + HO_V;

    auto load_stage = [&](int s, int kk0) {
        uint32_t base = sbase + (uint32_t)(s * FA_STAGE);
        for (int i = tid; i < 128 * 8; i += 256) {
            int row = i >> 3, c = i & 7;
            cpasync16(base + (uint32_t)(row * KSTR + c * 8) * 2,
                      Kp + ((long)bh * SS + kk0 + row) * 64 + c * 8);
        }
        for (int i = tid; i < 64 * 16; i += 256) {
            int row = i >> 4, c = i & 15;
            cpasync16(base + (uint32_t)KBYTES + (uint32_t)(row * VSTR + c * 8) * 2,
                      Vp + ((long)bh * HDIM + row) * SS + kk0 + c * 8);
        }
    };

    load_stage(0, 0);
    cp_commit();
    load_stage(1, 128);
    cp_commit();

    // Q fragments (layout-exact register loads) — overlap with cp.async stages
    uint32_t qf[4][4];
    {
        long r0 = (long)bh * SS + m0 + warp * 16 + tg;
        #pragma unroll
        for (int ks = 0; ks < 4; ks++) {
            int c0 = ks * 16 + tp * 2;
            qf[ks][0] = *(const uint32_t*)&Q[r0 * 64 + c0];
            qf[ks][1] = *(const uint32_t*)&Q[(r0 + 8) * 64 + c0];
            qf[ks][2] = *(const uint32_t*)&Q[r0 * 64 + c0 + 8];
            qf[ks][3] = *(const uint32_t*)&Q[(r0 + 8) * 64 + c0 + 8];
        }
    }

    float Oacc[8][4];
    #pragma unroll
    for (int i = 0; i < 8; i++)
        #pragma unroll
        for (int q = 0; q < 4; q++) Oacc[i][q] = 0.f;
    float mrun[2] = { -1e30f, -1e30f };
    float lrun[2] = { 0.f, 0.f };

    int s = 0;
    for (int it = 0; it < 16; ++it) {
        __syncthreads();   // all warps done reading stage (it+2)%3 from iter it-1
        if (it + 2 < 16) {
            int s2 = s + 2; if (s2 >= 3) s2 -= 3;
            load_stage(s2, (it + 2) * 128);
            cp_commit();
        }
        if (it < 14) cp_wait<2>(); else if (it == 14) cp_wait<1>(); else cp_wait<0>();

        uint32_t base = sbase + (uint32_t)(s * FA_STAGE);

        // ---- S = Q K^T (scale folded in Q) ----
        float sc[16][4];
        #pragma unroll
        for (int i = 0; i < 16; i++)
            #pragma unroll
            for (int q = 0; q < 4; q++) sc[i][q] = 0.f;

        #pragma unroll
        for (int ks = 0; ks < 4; ks++) {
            #pragma unroll
            for (int nf2 = 0; nf2 < 8; nf2++) {
                int r = nf2 * 16 + (lane & 15);
                uint32_t t[4], b0[2], b1[2];
                ldm_x4(t, base + (uint32_t)(r * KSTR + ks * 16 + (lane >> 4) * 8) * 2);
                b0[0] = t[0]; b0[1] = t[2];
                b1[0] = t[1]; b1[1] = t[3];
                mma16816(sc[2 * nf2],     qf[ks], b0);
                mma16816(sc[2 * nf2 + 1], qf[ks], b1);
            }
        }

        // ---- online softmax (exp2 domain, raw MUFU) ----
        float mx0 = mrun[0], mx1 = mrun[1];
        #pragma unroll
        for (int nf = 0; nf < 16; nf++) {
            mx0 = fmaxf(mx0, fmaxf(sc[nf][0], sc[nf][1]));
            mx1 = fmaxf(mx1, fmaxf(sc[nf][2], sc[nf][3]));
        }
        mx0 = fmaxf(mx0, __shfl_xor_sync(0xffffffffu, mx0, 1));
        mx0 = fmaxf(mx0, __shfl_xor_sync(0xffffffffu, mx0, 2));
        mx1 = fmaxf(mx1, __shfl_xor_sync(0xffffffffu, mx1, 1));
        mx1 = fmaxf(mx1, __shfl_xor_sync(0xffffffffu, mx1, 2));

        float alpha0 = ex2(mrun[0] - mx0);
        float alpha1 = ex2(mrun[1] - mx1);
        mrun[0] = mx0; mrun[1] = mx1;

        float sum0 = 0.f, sum1 = 0.f;
        #pragma unroll
        for (int nf = 0; nf < 16; nf++) {
            sc[nf][0] = ex2(sc[nf][0] - mx0);
            sc[nf][1] = ex2(sc[nf][1] - mx0);
            sc[nf][2] = ex2(sc[nf][2] - mx1);
            sc[nf][3] = ex2(sc[nf][3] - mx1);
            sum0 += sc[nf][0] + sc[nf][1];
            sum1 += sc[nf][2] + sc[nf][3];
        }
        sum0 += __shfl_xor_sync(0xffffffffu, sum0, 1);
        sum0 += __shfl_xor_sync(0xffffffffu, sum0, 2);
        sum1 += __shfl_xor_sync(0xffffffffu, sum1, 1);
        sum1 += __shfl_xor_sync(0xffffffffu, sum1, 2);
        lrun[0] = lrun[0] * alpha0 + sum0;
        lrun[1] = lrun[1] * alpha1 + sum1;

        #pragma unroll
        for (int nf = 0; nf < 8; nf++) {
            Oacc[nf][0] *= alpha0; Oacc[nf][1] *= alpha0;
            Oacc[nf][2] *= alpha1; Oacc[nf][3] *= alpha1;
        }

        // ---- O += P V ----
        #pragma unroll
        for (int ks = 0; ks < 8; ks++) {
            int u = 2 * ks, vt = 2 * ks + 1;
            uint32_t af[4];
            af[0] = pack2h(sc[u][0],  sc[u][1]);
            af[1] = pack2h(sc[u][2],  sc[u][3]);
            af[2] = pack2h(sc[vt][0], sc[vt][1]);
            af[3] = pack2h(sc[vt][2], sc[vt][3]);
            #pragma unroll
            for (int nf2 = 0; nf2 < 4; nf2++) {
                int r = nf2 * 16 + (lane & 15);
                uint32_t t[4], b0[2], b1[2];
                ldm_x4(t, base + (uint32_t)KBYTES
                           + (uint32_t)(r * VSTR + ks * 16 + (lane >> 4) * 8) * 2);
                b0[0] = t[0]; b0[1] = t[2];
                b1[0] = t[1]; b1[1] = t[3];
                mma16816(Oacc[2 * nf2],     af, b0);
                mma16816(Oacc[2 * nf2 + 1], af, b1);
            }
        }
        if (++s >= 3) s -= 3;
    }

    // ---- epilogue ----
    float inv0 = 1.0f / lrun[0], inv1 = 1.0f / lrun[1];
    int b = bh / HH, h = bh % HH;
    long tok0 = (long)b * SS + m0 + warp * 16 + tg;
    __half* O = h_scratch + HO_OC;
    #pragma unroll
    for (int nf = 0; nf < 8; nf++) {
        int col = h * HDIM + nf * 8 + tp * 2;
        *(uint32_t*)&O[tok0 * DD + col] =
            pack2h(Oacc[nf][0] * inv0, Oacc[nf][1] * inv0);
        *(uint32_t*)&O[(tok0 + 8) * DD + col] =
            pack2h(Oacc[nf][2] * inv1, Oacc[nf][3] * inv1);
    }
}

// ---------------- launch ----------------
extern "C" void kernel_launch(void* const* d_in, const int* in_sizes, int n_in,
                              void* d_out, int out_size) {
    const float* x   = (const float*)d_in[0];
    const float* Wq  = (const float*)d_in[1];
    const float* bq  = (const float*)d_in[2];
    const float* Wk  = (const float*)d_in[3];
    const float* bk  = (const float*)d_in[4];
    const float* Wv  = (const float*)d_in[5];
    const float* bv  = (const float*)d_in[6];
    const float* Wo  = (const float*)d_in[7];
    const float* bo  = (const float*)d_in[8];
    const float* W1  = (const float*)d_in[9];
    const float* b1  = (const float*)d_in[10];
    const float* W2  = (const float*)d_in[11];
    const float* b2  = (const float*)d_in[12];
    const float* g1  = (const float*)d_in[13];
    const float* be1 = (const float*)d_in[14];
    const float* g2  = (const float*)d_in[15];
    const float* be2 = (const float*)d_in[16];
    float* out = (float*)d_out;

    static __half* hs = nullptr;
    static float* fs = nullptr;
    if (!hs) {
        void* p;
        cudaGetSymbolAddress(&p, h_scratch); hs = (__half*)p;
        cudaGetSymbolAddress(&p, f_scratch); fs = (float*)p;
    }

    const int SMEM_GEMM   = 3 * ((128 + 128) * 40) * 2;  // 61440 B
    const int SMEM_GEMM64 = 3 * ((128 + 64) * 40) * 2;   // 46080 B
    static bool attrDone = false;
    if (!attrDone) {
        cudaFuncSetAttribute((const void*)mma_gemm<128,128,32,2,4,1>,
                             cudaFuncAttributeMaxDynamicSharedMemorySize, SMEM_GEMM);
        cudaFuncSetAttribute((const void*)mma_gemm<128,128,32,2,4,3>,
                             cudaFuncAttributeMaxDynamicSharedMemorySize, SMEM_GEMM);
        cudaFuncSetAttribute((const void*)mma_gemm<128,64,32,4,2,0>,
                             cudaFuncAttributeMaxDynamicSharedMemorySize, SMEM_GEMM64);
        cudaFuncSetAttribute((const void*)flash_attn,
                             cudaFuncAttributeMaxDynamicSharedMemorySize, FA_SMEM);
        attrDone = true;
    }

    // 1) weight/bias packing + conversion
    pack_wqkv<<<(unsigned)((2304L * 768 + 255) / 256), 256>>>(Wq, Wk, Wv, bq, bk, bv);
    transpose_w<<<dim3(768 / 32, 768 / 32), dim3(32, 8)>>>(Wo, 768, 768, HO_WO);
    transpose_w<<<dim3(3072 / 32, 768 / 32), dim3(32, 8)>>>(W1, 768, 3072, HO_W1);
    transpose_w<<<dim3(768 / 32, 3072 / 32), dim3(32, 8)>>>(W2, 3072, 768, HO_W2);

    // 2) LN1 -> h (fp16)
    ln_fp16<<<NTOK, 256>>>(x, 0, g1, be1, HO_H);

    // 3) QKV GEMM with scatter epilogue (Q pre-scaled by 0.125*log2e)
    mma_gemm<128,128,32,2,4,1><<<dim3(18, 64), 256, SMEM_GEMM>>>(
        hs + HO_H, hs + HO_WQKV, fs + FO_BQKV, nullptr,
        NTOK, 3 * DD, DD, DD, DD, 0);

    // 4) fused flash attention -> Oc (concat layout, fp16)
    flash_attn<<<dim3(16, BH), 256, FA_SMEM>>>();

    // 5) O-proj -> a (fp32)  [BN=64 tiles: 768 CTAs, better wave fill]
    mma_gemm<128,64,32,4,2,0><<<dim3(12, 64), 256, SMEM_GEMM64>>>(
        hs + HO_OC, hs + HO_WO, bo, fs + FO_A,
        NTOK, DD, DD, DD, DD, DD);

    // 6) LN2 -> h2 (fp16)
    ln_fp16<<<NTOK, 256>>>(nullptr, 1, g2, be2, HO_H2);

    // 7) MLP1 + GELU -> f (fp16)
    mma_gemm<128,128,32,2,4,3><<<dim3(24, 64), 256, SMEM_GEMM>>>(
        hs + HO_H2, hs + HO_W1, b1, nullptr,
        NTOK, FF, DD, DD, DD, 0);

    // 8) MLP2 -> out (fp32)  [BN=64 tiles]
    mma_gemm<128,64,32,4,2,0><<<dim3(12, 64), 256, SMEM_GEMM64>>>(
        hs + HO_F, hs + HO_W2, b2, out,
        NTOK, DD, FF, FF, FF, DD);
}

// round 12
// speedup vs baseline: 1.0367x; 1.0367x over previous
#include <cuda_runtime.h>
#include <cuda_fp16.h>
#include <math.h>
#include <stdint.h>

// ---------------- problem constants ----------------
#define BB   4
#define SS   2048
#define DD   768
#define HH   12
#define HDIM 64
#define FF   3072
#define NTOK 8192
#define BH   48

#define SCALEQ 0.18033688011112042f   // 0.125 * log2(e)

// ---------------- fp16 scratch ----------------
#define N_H     6291456L
#define N_WQKV  1769472L
#define N_QKV1  6291456L
#define N_OC    6291456L
#define N_WO    589824L
#define N_H2    6291456L
#define N_W1    2359296L
#define N_F     25165824L
#define N_W2    2359296L

#define HO_H     0L
#define HO_WQKV  (HO_H    + N_H)
#define HO_Q     (HO_WQKV + N_WQKV)
#define HO_K     (HO_Q    + N_QKV1)
#define HO_V     (HO_K    + N_QKV1)
#define HO_OC    (HO_V    + N_QKV1)
#define HO_WO    (HO_OC   + N_OC)
#define HO_H2    (HO_WO   + N_WO)
#define HO_W1    (HO_H2   + N_H2)
#define HO_F     (HO_W1   + N_W1)
#define HO_W2    (HO_F    + N_F)
#define H_TOTAL  (HO_W2   + N_W2)

#define FO_A      0L
#define FO_BQKV   6291456L
#define F_TOTAL   (FO_BQKV + 2304L)

__device__ __align__(16) __half h_scratch[H_TOTAL];
__device__ __align__(16) float  f_scratch[F_TOTAL];

// ---------------- small helpers ----------------
__device__ __forceinline__ uint32_t pack2h(float x, float y) {
    __half2 h = __floats2half2_rn(x, y);
    return *(uint32_t*)&h;
}

__device__ __forceinline__ float ex2(float x) {
    float r;
    asm("ex2.approx.ftz.f32 %0, %1;" : "=f"(r) : "f"(x));
    return r;
}

__device__ __forceinline__ float gelu_exact(float x) {
    return 0.5f * x * (1.0f + erff(x * 0.70710678118654752f));
}

__device__ __forceinline__ void cpasync16(uint32_t dst, const void* src) {
    asm volatile("cp.async.cg.shared.global [%0], [%1], 16;\n" :: "r"(dst), "l"(src));
}
__device__ __forceinline__ void cp_commit() {
    asm volatile("cp.async.commit_group;\n");
}
template<int N> __device__ __forceinline__ void cp_wait() {
    asm volatile("cp.async.wait_group %0;\n" :: "n"(N));
}
__device__ __forceinline__ void ldm_x4(uint32_t* r, uint32_t addr) {
    asm volatile("ldmatrix.sync.aligned.m8n8.x4.shared.b16 {%0,%1,%2,%3}, [%4];\n"
                 : "=r"(r[0]), "=r"(r[1]), "=r"(r[2]), "=r"(r[3]) : "r"(addr));
}
__device__ __forceinline__ void mma16816(float* d, const uint32_t* a, const uint32_t* b) {
    asm volatile("mma.sync.aligned.m16n8k16.row.col.f32.f16.f16.f32 "
                 "{%0,%1,%2,%3},{%4,%5,%6,%7},{%8,%9},{%0,%1,%2,%3};\n"
                 : "+f"(d[0]), "+f"(d[1]), "+f"(d[2]), "+f"(d[3])
                 : "r"(a[0]), "r"(a[1]), "r"(a[2]), "r"(a[3]), "r"(b[0]), "r"(b[1]));
}

// ---------------- packing / conversion kernels ----------------
__global__ void pack_wqkv(const float* __restrict__ Wq, const float* __restrict__ Wk,
                          const float* __restrict__ Wv, const float* __restrict__ bq,
                          const float* __restrict__ bk, const float* __restrict__ bv) {
    long idx = (long)blockIdx.x * blockDim.x + threadIdx.x;
    if (idx < 2304L * 768) {
        int n = (int)(idx / 768), k = (int)(idx % 768);
        int which = n / DD;
        int r = n - which * DD;
        int h = r >> 6, e = r & 63;
        const float* W = (which == 0) ? Wq : (which == 1) ? Wk : Wv;
        h_scratch[HO_WQKV + idx] =
            __float2half(W[(long)h * (DD * HDIM) + (long)k * HDIM + e]);
    }
    if (idx < 3 * DD) {
        int which = (int)(idx / DD), r = (int)(idx % DD);
        const float* b = (which == 0) ? bq : (which == 1) ? bk : bv;
        f_scratch[FO_BQKV + idx] = b[r];
    }
}

// tiled transpose: out[n*K + k] = W[k*N + n]
__global__ void transpose_w(const float* __restrict__ W, int K, int N, long outOff) {
    __shared__ float t[32][33];
    int bx = blockIdx.x * 32, by = blockIdx.y * 32;
    int tx = threadIdx.x, ty = threadIdx.y;  // block (32,8)
    #pragma unroll
    for (int j = 0; j < 32; j += 8)
        t[ty + j][tx] = W[(long)(by + ty + j) * N + bx + tx];
    __syncthreads();
    __half* o = h_scratch + outOff;
    #pragma unroll
    for (int j = 0; j < 32; j += 8)
        o[(long)(bx + ty + j) * K + by + tx] = __float2half(t[tx][ty + j]);
}

// LayerNorm over rows of 768, output fp16
__global__ void ln_fp16(const float* __restrict__ xext, int useScratch,
                        const float* __restrict__ g, const float* __restrict__ b,
                        long outOff) {
    const float* src = (useScratch ? (const float*)(f_scratch + FO_A) : xext)
                       + (long)blockIdx.x * DD;
    int tid = threadIdx.x;
    float s = 0.f, s2 = 0.f;
    for (int i = tid; i < DD; i += 256) { float v = src[i]; s += v; s2 += v * v; }
    #pragma unroll
    for (int off = 16; off; off >>= 1) {
        s  += __shfl_down_sync(0xffffffffu, s,  off);
        s2 += __shfl_down_sync(0xffffffffu, s2, off);
    }
    __shared__ float sh[2][8];
    int wid = tid >> 5, lane = tid & 31;
    if (lane == 0) { sh[0][wid] = s; sh[1][wid] = s2; }
    __syncthreads();
    if (tid == 0) {
        float ts = 0.f, ts2 = 0.f;
        #pragma unroll
        for (int i = 0; i < 8; i++) { ts += sh[0][i]; ts2 += sh[1][i]; }
        float mean = ts * (1.0f / DD);
        float var = ts2 * (1.0f / DD) - mean * mean;
        sh[0][0] = mean;
        sh[1][0] = rsqrtf(var + 1e-5f);
    }
    __syncthreads();
    float mean = sh[0][0], rstd = sh[1][0];
    long base = outOff + (long)blockIdx.x * DD;
    for (int i = tid; i < DD; i += 256) {
        float v = (src[i] - mean) * rstd * g[i] + b[i];
        h_scratch[base + i] = __float2half(v);
    }
}

// ---------------- fp16 tensor-core GEMM (3-stage pipeline) ----------------
// A: [M,K] K-major fp16.  B: [N,K] K-major fp16.
// MODE 0: fp32 out (+bias).  MODE 1: QKV scatter (+bias, Q scaled).  MODE 3: gelu -> f fp16
template<int BM, int BN, int BK, int WM, int WN, int MODE>
__global__ void __launch_bounds__(256, 2)
mma_gemm(const __half* __restrict__ A, const __half* __restrict__ B,
         const float* __restrict__ bias, float* __restrict__ Cf,
         int M, int N, int K, int lda, int ldb, int ldc) {
    constexpr int BKP = BK + 8;
    constexpr int WTM = BM / WM, WTN = BN / WN;
    constexpr int MF = WTM / 16, NF = WTN / 8;
    constexpr int STAGE = (BM + BN) * BKP;     // halfs per stage

    extern __shared__ __half smem[];
    const int tid = threadIdx.x, lane = tid & 31, warp = tid >> 5;
    const int wm = warp % WM, wn = warp / WM;
    const int m0 = blockIdx.y * BM, n0 = blockIdx.x * BN;

    uint32_t sbase = (uint32_t)__cvta_generic_to_shared(smem);

    auto load_stage = [&](int s, int k0) {
        uint32_t base = sbase + (uint32_t)(s * STAGE) * 2;
        #pragma unroll 2
        for (int i = tid; i < BM * (BK / 8); i += 256) {
            int row = i / (BK / 8), c = i % (BK / 8);
            cpasync16(base + (uint32_t)(row * BKP + c * 8) * 2,
                      A + (long)(m0 + row) * lda + k0 + c * 8);
        }
        #pragma unroll 2
        for (int i = tid; i < BN * (BK / 8); i += 256) {
            int row = i / (BK / 8), c = i % (BK / 8);
            cpasync16(base + (uint32_t)(BM * BKP + row * BKP + c * 8) * 2,
                      B + (long)(n0 + row) * ldb + k0 + c * 8);
        }
    };

    float acc[MF][NF][4];
    #pragma unroll
    for (int i = 0; i < MF; i++)
        #pragma unroll
        for (int j = 0; j < NF; j++)
            #pragma unroll
            for (int q = 0; q < 4; q++) acc[i][j][q] = 0.f;

    const int nIter = K / BK;
    load_stage(0, 0); cp_commit();
    load_stage(1, BK); cp_commit();

    int s = 0;
    for (int it = 0; it < nIter; ++it) {
        if (it + 1 < nIter) cp_wait<1>(); else cp_wait<0>();
        __syncthreads();
        if (it + 2 < nIter) {
            int s2 = s + 2; if (s2 >= 3) s2 -= 3;
            load_stage(s2, (it + 2) * BK);
            cp_commit();
        }

        uint32_t base = sbase + (uint32_t)(s * STAGE) * 2;
        #pragma unroll
        for (int kk = 0; kk < BK; kk += 16) {
            uint32_t af[MF][4], bf[NF][2];
            #pragma unroll
            for (int mf = 0; mf < MF; mf++) {
                int r = wm * WTM + mf * 16 + (lane & 15);
                ldm_x4(af[mf], base + (uint32_t)(r * BKP + kk + (lane >> 4) * 8) * 2);
            }
            #pragma unroll
            for (int nf2 = 0; nf2 < NF / 2; nf2++) {
                int r = wn * WTN + nf2 * 16 + (lane & 15);
                uint32_t t[4];
                ldm_x4(t, base + (uint32_t)(BM * BKP + r * BKP + kk + (lane >> 4) * 8) * 2);
                bf[2 * nf2][0] = t[0]; bf[2 * nf2][1] = t[2];
                bf[2 * nf2 + 1][0] = t[1]; bf[2 * nf2 + 1][1] = t[3];
            }
            #pragma unroll
            for (int mf = 0; mf < MF; mf++)
                #pragma unroll
                for (int nf = 0; nf < NF; nf++)
                    mma16816(acc[mf][nf], af[mf], bf[nf]);
        }
        if (++s >= 3) s -= 3;
    }

    const int tg = lane >> 2, tp = lane & 3;
    #pragma unroll
    for (int mf = 0; mf < MF; mf++) {
        #pragma unroll
        for (int nf = 0; nf < NF; nf++) {
            int mA = m0 + wm * WTM + mf * 16 + tg;
            int nA = n0 + wn * WTN + nf * 8 + tp * 2;
            float v0 = acc[mf][nf][0], v1 = acc[mf][nf][1];
            float v2 = acc[mf][nf][2], v3 = acc[mf][nf][3];
            if (bias) {
                float b0 = bias[nA], b1 = bias[nA + 1];
                v0 += b0; v1 += b1; v2 += b0; v3 += b1;
            }
            if (MODE == 0) {
                *(float2*)&Cf[(long)mA * ldc + nA] = make_float2(v0, v1);
                *(float2*)&Cf[(long)(mA + 8) * ldc + nA] = make_float2(v2, v3);
            } else if (MODE == 1) {
                int which = nA / DD;
                int r = nA - which * DD;
                int h = r >> 6, e = r & 63;
                if (which == 2) {
                    // V transposed: strided scalar stores
                    #pragma unroll
                    for (int q = 0; q < 4; q++) {
                        int m = mA + (q >> 1) * 8;
                        int eq = e + (q & 1);
                        float v = (q == 0) ? v0 : (q == 1) ? v1 : (q == 2) ? v2 : v3;
                        int bh = (m >> 11) * HH + h;
                        h_scratch[HO_V + ((long)bh * HDIM + eq) * SS + (m & 2047)] =
                            __float2half(v);
                    }
                } else {
                    float scl = (which == 0) ? SCALEQ : 1.0f;
                    long off = (which == 0) ? HO_Q : HO_K;
                    int bh0 = (mA >> 11) * HH + h;
                    long i0 = ((long)bh0 * SS + (mA & 2047)) * HDIM + e;
                    *(uint32_t*)&h_scratch[off + i0] = pack2h(v0 * scl, v1 * scl);
                    int m8 = mA + 8;
                    int bh1 = (m8 >> 11) * HH + h;
                    long i1 = ((long)bh1 * SS + (m8 & 2047)) * HDIM + e;
                    *(uint32_t*)&h_scratch[off + i1] = pack2h(v2 * scl, v3 * scl);
                }
            } else { // MODE 3: gelu -> f (packed u32 stores)
                *(uint32_t*)&h_scratch[HO_F + (long)mA * FF + nA] =
                    pack2h(gelu_exact(v0), gelu_exact(v1));
                *(uint32_t*)&h_scratch[HO_F + (long)(mA + 8) * FF + nA] =
                    pack2h(gelu_exact(v2), gelu_exact(v3));
            }
        }
    }
}

// ---------------- flash attention (fp16, BM=64, 4 warps, 3 CTAs/SM) ----------------
#define KSTR 72
#define VSTR 136
#define KBYTES (128 * KSTR * 2)           // 18432
#define VBYTES (64 * VSTR * 2)            // 17408
#define FA_STAGE (KBYTES + VBYTES)        // 35840
#define FA_SMEM  (2 * FA_STAGE)           // 71680

__global__ void __launch_bounds__(128, 3)
flash_attn() {
    extern __shared__ char fsm[];
    uint32_t sbase = (uint32_t)__cvta_generic_to_shared(fsm);
    const int tid = threadIdx.x, lane = tid & 31, warp = tid >> 5;   // warp 0..3
    const int tg = lane >> 2, tp = lane & 3;
    const int m0 = blockIdx.x * 64;
    const int bh = blockIdx.y;

    const __half* Q = h_scratch + HO_Q;
    const __half* Kp = h_scratch + HO_K;
    const __half* Vp = h_scratch + HO_V;

    auto load_stage = [&](int s, int kk0) {
        uint32_t base = sbase + (uint32_t)(s * FA_STAGE);
        for (int i = tid; i < 128 * 8; i += 128) {
            int row = i >> 3, c = i & 7;
            cpasync16(base + (uint32_t)(row * KSTR + c * 8) * 2,
                      Kp + ((long)bh * SS + kk0 + row) * 64 + c * 8);
        }
        for (int i = tid; i < 64 * 16; i += 128) {
            int row = i >> 4, c = i & 15;
            cpasync16(base + (uint32_t)KBYTES + (uint32_t)(row * VSTR + c * 8) * 2,
                      Vp + ((long)bh * HDIM + row) * SS + kk0 + c * 8);
        }
    };

    load_stage(0, 0);
    cp_commit();

    // Q fragments (layout-exact register loads) — overlap with stage-0 cp.async
    uint32_t qf[4][4];
    {
        long r0 = (long)bh * SS + m0 + warp * 16 + tg;
        #pragma unroll
        for (int ks = 0; ks < 4; ks++) {
            int c0 = ks * 16 + tp * 2;
            qf[ks][0] = *(const uint32_t*)&Q[r0 * 64 + c0];
            qf[ks][1] = *(const uint32_t*)&Q[(r0 + 8) * 64 + c0];
            qf[ks][2] = *(const uint32_t*)&Q[r0 * 64 + c0 + 8];
            qf[ks][3] = *(const uint32_t*)&Q[(r0 + 8) * 64 + c0 + 8];
        }
    }

    float Oacc[8][4];
    #pragma unroll
    for (int i = 0; i < 8; i++)
        #pragma unroll
        for (int q = 0; q < 4; q++) Oacc[i][q] = 0.f;
    float mrun[2] = { -1e30f, -1e30f };
    float lrun[2] = { 0.f, 0.f };

    for (int it = 0; it < 16; ++it) {
        int s = it & 1;
        if (it + 1 < 16) {
            load_stage(s ^ 1, (it + 1) * 128);
            cp_commit();
            cp_wait<1>();
        } else {
            cp_wait<0>();
        }
        __syncthreads();

        uint32_t base = sbase + (uint32_t)(s * FA_STAGE);

        // ---- S = Q K^T (scale folded in Q) ----
        float sc[16][4];
        #pragma unroll
        for (int i = 0; i < 16; i++)
            #pragma unroll
            for (int q = 0; q < 4; q++) sc[i][q] = 0.f;

        #pragma unroll
        for (int ks = 0; ks < 4; ks++) {
            #pragma unroll
            for (int nf2 = 0; nf2 < 8; nf2++) {
                int r = nf2 * 16 + (lane & 15);
                uint32_t t[4], b0[2], b1[2];
                ldm_x4(t, base + (uint32_t)(r * KSTR + ks * 16 + (lane >> 4) * 8) * 2);
                b0[0] = t[0]; b0[1] = t[2];
                b1[0] = t[1]; b1[1] = t[3];
                mma16816(sc[2 * nf2],     qf[ks], b0);
                mma16816(sc[2 * nf2 + 1], qf[ks], b1);
            }
        }

        // ---- online softmax (exp2 domain, raw MUFU) ----
        float mx0 = mrun[0], mx1 = mrun[1];
        #pragma unroll
        for (int nf = 0; nf < 16; nf++) {
            mx0 = fmaxf(mx0, fmaxf(sc[nf][0], sc[nf][1]));
            mx1 = fmaxf(mx1, fmaxf(sc[nf][2], sc[nf][3]));
        }
        mx0 = fmaxf(mx0, __shfl_xor_sync(0xffffffffu, mx0, 1));
        mx0 = fmaxf(mx0, __shfl_xor_sync(0xffffffffu, mx0, 2));
        mx1 = fmaxf(mx1, __shfl_xor_sync(0xffffffffu, mx1, 1));
        mx1 = fmaxf(mx1, __shfl_xor_sync(0xffffffffu, mx1, 2));

        float alpha0 = ex2(mrun[0] - mx0);
        float alpha1 = ex2(mrun[1] - mx1);
        mrun[0] = mx0; mrun[1] = mx1;

        float sum0 = 0.f, sum1 = 0.f;
        #pragma unroll
        for (int nf = 0; nf < 16; nf++) {
            sc[nf][0] = ex2(sc[nf][0] - mx0);
            sc[nf][1] = ex2(sc[nf][1] - mx0);
            sc[nf][2] = ex2(sc[nf][2] - mx1);
            sc[nf][3] = ex2(sc[nf][3] - mx1);
            sum0 += sc[nf][0] + sc[nf][1];
            sum1 += sc[nf][2] + sc[nf][3];
        }
        sum0 += __shfl_xor_sync(0xffffffffu, sum0, 1);
        sum0 += __shfl_xor_sync(0xffffffffu, sum0, 2);
        sum1 += __shfl_xor_sync(0xffffffffu, sum1, 1);
        sum1 += __shfl_xor_sync(0xffffffffu, sum1, 2);
        lrun[0] = lrun[0] * alpha0 + sum0;
        lrun[1] = lrun[1] * alpha1 + sum1;

        #pragma unroll
        for (int nf = 0; nf < 8; nf++) {
            Oacc[nf][0] *= alpha0; Oacc[nf][1] *= alpha0;
            Oacc[nf][2] *= alpha1; Oacc[nf][3] *= alpha1;
        }

        // ---- O += P V ----
        #pragma unroll
        for (int ks = 0; ks < 8; ks++) {
            int u = 2 * ks, vt = 2 * ks + 1;
            uint32_t af[4];
            af[0] = pack2h(sc[u][0],  sc[u][1]);
            af[1] = pack2h(sc[u][2],  sc[u][3]);
            af[2] = pack2h(sc[vt][0], sc[vt][1]);
            af[3] = pack2h(sc[vt][2], sc[vt][3]);
            #pragma unroll
            for (int nf2 = 0; nf2 < 4; nf2++) {
                int r = nf2 * 16 + (lane & 15);
                uint32_t t[4], b0[2], b1[2];
                ldm_x4(t, base + (uint32_t)KBYTES
                           + (uint32_t)(r * VSTR + ks * 16 + (lane >> 4) * 8) * 2);
                b0[0] = t[0]; b0[1] = t[2];
                b1[0] = t[1]; b1[1] = t[3];
                mma16816(Oacc[2 * nf2],     af, b0);
                mma16816(Oacc[2 * nf2 + 1], af, b1);
            }
        }
        __syncthreads();
    }

    // ---- epilogue ----
    float inv0 = 1.0f / lrun[0], inv1 = 1.0f / lrun[1];
    int b = bh / HH, h = bh % HH;
    long tok0 = (long)b * SS + m0 + warp * 16 + tg;
    __half* O = h_scratch + HO_OC;
    #pragma unroll
    for (int nf = 0; nf < 8; nf++) {
        int col = h * HDIM + nf * 8 + tp * 2;
        *(uint32_t*)&O[tok0 * DD + col] =
            pack2h(Oacc[nf][0] * inv0, Oacc[nf][1] * inv0);
        *(uint32_t*)&O[(tok0 + 8) * DD + col] =
            pack2h(Oacc[nf][2] * inv1, Oacc[nf][3] * inv1);
    }
}

// ---------------- launch ----------------
extern "C" void kernel_launch(void* const* d_in, const int* in_sizes, int n_in,
                              void* d_out, int out_size) {
    const float* x   = (const float*)d_in[0];
    const float* Wq  = (const float*)d_in[1];
    const float* bq  = (const float*)d_in[2];
    const float* Wk  = (const float*)d_in[3];
    const float* bk  = (const float*)d_in[4];
    const float* Wv  = (const float*)d_in[5];
    const float* bv  = (const float*)d_in[6];
    const float* Wo  = (const float*)d_in[7];
    const float* bo  = (const float*)d_in[8];
    const float* W1  = (const float*)d_in[9];
    const float* b1  = (const float*)d_in[10];
    const float* W2  = (const float*)d_in[11];
    const float* b2  = (const float*)d_in[12];
    const float* g1  = (const float*)d_in[13];
    const float* be1 = (const float*)d_in[14];
    const float* g2  = (const float*)d_in[15];
    const float* be2 = (const float*)d_in[16];
    float* out = (float*)d_out;

    static __half* hs = nullptr;
    static float* fs = nullptr;
    if (!hs) {
        void* p;
        cudaGetSymbolAddress(&p, h_scratch); hs = (__half*)p;
        cudaGetSymbolAddress(&p, f_scratch); fs = (float*)p;
    }

    const int SMEM_GEMM   = 3 * ((128 + 128) * 40) * 2;  // 61440 B
    const int SMEM_GEMM64 = 3 * ((128 + 64) * 40) * 2;   // 46080 B
    static bool attrDone = false;
    if (!attrDone) {
        cudaFuncSetAttribute((const void*)mma_gemm<128,128,32,2,4,1>,
                             cudaFuncAttributeMaxDynamicSharedMemorySize, SMEM_GEMM);
        cudaFuncSetAttribute((const void*)mma_gemm<128,128,32,2,4,3>,
                             cudaFuncAttributeMaxDynamicSharedMemorySize, SMEM_GEMM);
        cudaFuncSetAttribute((const void*)mma_gemm<128,64,32,4,2,0>,
                             cudaFuncAttributeMaxDynamicSharedMemorySize, SMEM_GEMM64);
        cudaFuncSetAttribute((const void*)flash_attn,
                             cudaFuncAttributeMaxDynamicSharedMemorySize, FA_SMEM);
        attrDone = true;
    }

    // 1) weight/bias packing + conversion
    pack_wqkv<<<(unsigned)((2304L * 768 + 255) / 256), 256>>>(Wq, Wk, Wv, bq, bk, bv);
    transpose_w<<<dim3(768 / 32, 768 / 32), dim3(32, 8)>>>(Wo, 768, 768, HO_WO);
    transpose_w<<<dim3(3072 / 32, 768 / 32), dim3(32, 8)>>>(W1, 768, 3072, HO_W1);
    transpose_w<<<dim3(768 / 32, 3072 / 32), dim3(32, 8)>>>(W2, 3072, 768, HO_W2);

    // 2) LN1 -> h (fp16)
    ln_fp16<<<NTOK, 256>>>(x, 0, g1, be1, HO_H);

    // 3) QKV GEMM with scatter epilogue (Q pre-scaled by 0.125*log2e)
    mma_gemm<128,128,32,2,4,1><<<dim3(18, 64), 256, SMEM_GEMM>>>(
        hs + HO_H, hs + HO_WQKV, fs + FO_BQKV, nullptr,
        NTOK, 3 * DD, DD, DD, DD, 0);

    // 4) fused flash attention -> Oc (BM=64, 3 CTAs/SM)
    flash_attn<<<dim3(32, BH), 128, FA_SMEM>>>();

    // 5) O-proj -> a (fp32)  [BN=64 tiles]
    mma_gemm<128,64,32,4,2,0><<<dim3(12, 64), 256, SMEM_GEMM64>>>(
        hs + HO_OC, hs + HO_WO, bo, fs + FO_A,
        NTOK, DD, DD, DD, DD, DD);

    // 6) LN2 -> h2 (fp16)
    ln_fp16<<<NTOK, 256>>>(nullptr, 1, g2, be2, HO_H2);

    // 7) MLP1 + GELU -> f (fp16)
    mma_gemm<128,128,32,2,4,3><<<dim3(24, 64), 256, SMEM_GEMM>>>(
        hs + HO_H2, hs + HO_W1, b1, nullptr,
        NTOK, FF, DD, DD, DD, 0);

    // 8) MLP2 -> out (fp32)  [BN=64 tiles]
    mma_gemm<128,64,32,4,2,0><<<dim3(12, 64), 256, SMEM_GEMM64>>>(
        hs + HO_F, hs + HO_W2, b2, out,
        NTOK, DD, FF, FF, FF, DD);
}

// round 15
// speedup vs baseline: 1.1870x; 1.1449x over previous
#include <cuda_runtime.h>
#include <cuda_fp16.h>
#include <math.h>
#include <stdint.h>

// ---------------- problem constants ----------------
#define BB   4
#define SS   2048
#define DD   768
#define HH   12
#define HDIM 64
#define FF   3072
#define NTOK 8192
#define BH   48

#define SCALEQ 0.18033688011112042f   // 0.125 * log2(e)

// ---------------- fp16 scratch ----------------
#define N_H     6291456L
#define N_WQKV  1769472L
#define N_QKV1  6291456L
#define N_OC    6291456L
#define N_WO    589824L
#define N_H2    6291456L
#define N_W1    2359296L
#define N_F     25165824L
#define N_W2    2359296L

#define HO_H     0L
#define HO_WQKV  (HO_H    + N_H)
#define HO_Q     (HO_WQKV + N_WQKV)
#define HO_K     (HO_Q    + N_QKV1)
#define HO_V     (HO_K    + N_QKV1)
#define HO_OC    (HO_V    + N_QKV1)
#define HO_WO    (HO_OC   + N_OC)
#define HO_H2    (HO_WO   + N_WO)
#define HO_W1    (HO_H2   + N_H2)
#define HO_F     (HO_W1   + N_W1)
#define HO_W2    (HO_F    + N_F)
#define H_TOTAL  (HO_W2   + N_W2)

#define FO_A      0L
#define FO_BQKV   6291456L
#define F_TOTAL   (FO_BQKV + 2304L)

__device__ __align__(16) __half h_scratch[H_TOTAL];
__device__ __align__(16) float  f_scratch[F_TOTAL];

// ---------------- small helpers ----------------
__device__ __forceinline__ uint32_t pack2h(float x, float y) {
    __half2 h = __floats2half2_rn(x, y);
    return *(uint32_t*)&h;
}

__device__ __forceinline__ float ex2(float x) {
    float r;
    asm("ex2.approx.ftz.f32 %0, %1;" : "=f"(r) : "f"(x));
    return r;
}

__device__ __forceinline__ float gelu_exact(float x) {
    return 0.5f * x * (1.0f + erff(x * 0.70710678118654752f));
}

__device__ __forceinline__ void cpasync16(uint32_t dst, const void* src) {
    asm volatile("cp.async.cg.shared.global [%0], [%1], 16;\n" :: "r"(dst), "l"(src));
}
__device__ __forceinline__ void cp_commit() {
    asm volatile("cp.async.commit_group;\n");
}
template<int N> __device__ __forceinline__ void cp_wait() {
    asm volatile("cp.async.wait_group %0;\n" :: "n"(N));
}
__device__ __forceinline__ void ldm_x4(uint32_t* r, uint32_t addr) {
    asm volatile("ldmatrix.sync.aligned.m8n8.x4.shared.b16 {%0,%1,%2,%3}, [%4];\n"
                 : "=r"(r[0]), "=r"(r[1]), "=r"(r[2]), "=r"(r[3]) : "r"(addr));
}
__device__ __forceinline__ void mma16816(float* d, const uint32_t* a, const uint32_t* b) {
    asm volatile("mma.sync.aligned.m16n8k16.row.col.f32.f16.f16.f32 "
                 "{%0,%1,%2,%3},{%4,%5,%6,%7},{%8,%9},{%0,%1,%2,%3};\n"
                 : "+f"(d[0]), "+f"(d[1]), "+f"(d[2]), "+f"(d[3])
                 : "r"(a[0]), "r"(a[1]), "r"(a[2]), "r"(a[3]), "r"(b[0]), "r"(b[1]));
}

// ---------------- packing / conversion kernels ----------------
__global__ void pack_wqkv(const float* __restrict__ Wq, const float* __restrict__ Wk,
                          const float* __restrict__ Wv, const float* __restrict__ bq,
                          const float* __restrict__ bk, const float* __restrict__ bv) {
    long idx = (long)blockIdx.x * blockDim.x + threadIdx.x;
    if (idx < 2304L * 768) {
        int n = (int)(idx / 768), k = (int)(idx % 768);
        int which = n / DD;
        int r = n - which * DD;
        int h = r >> 6, e = r & 63;
        const float* W = (which == 0) ? Wq : (which == 1) ? Wk : Wv;
        h_scratch[HO_WQKV + idx] =
            __float2half(W[(long)h * (DD * HDIM) + (long)k * HDIM + e]);
    }
    if (idx < 3 * DD) {
        int which = (int)(idx / DD), r = (int)(idx % DD);
        const float* b = (which == 0) ? bq : (which == 1) ? bk : bv;
        f_scratch[FO_BQKV + idx] = b[r];
    }
}

// fused 3-way tiled transpose: out[n*K + k] = W[k*N + n] for Wo/W1/W2
__global__ void transpose3(const float* __restrict__ Wo, const float* __restrict__ W1,
                           const float* __restrict__ W2) {
    __shared__ float t[32][33];
    int id = blockIdx.x;
    const float* W;
    int K, N;
    long off;
    if (id < 576)        { W = Wo; K = 768;  N = 768;  off = HO_WO; }
    else if (id < 2880)  { id -= 576;  W = W1; K = 768;  N = 3072; off = HO_W1; }
    else                 { id -= 2880; W = W2; K = 3072; N = 768;  off = HO_W2; }
    int nbx = N / 32;
    int bx = (id % nbx) * 32, by = (id / nbx) * 32;
    int tx = threadIdx.x, ty = threadIdx.y;  // block (32,8)
    #pragma unroll
    for (int j = 0; j < 32; j += 8)
        t[ty + j][tx] = W[(long)(by + ty + j) * N + bx + tx];
    __syncthreads();
    __half* o = h_scratch + off;
    #pragma unroll
    for (int j = 0; j < 32; j += 8)
        o[(long)(bx + ty + j) * K + by + tx] = __float2half(t[tx][ty + j]);
}

// LayerNorm: warp per row, 8 rows per 256-thread block. grid = NTOK/8.
__global__ void ln_fp16(const float* __restrict__ xext, int useScratch,
                        const float* __restrict__ g, const float* __restrict__ b,
                        long outOff) {
    const int warp = threadIdx.x >> 5, lane = threadIdx.x & 31;
    const long row = (long)blockIdx.x * 8 + warp;
    const float* srcBase = useScratch ? (const float*)(f_scratch + FO_A) : xext;
    const float4* s4 = (const float4*)(srcBase + row * DD);

    float4 v[6];
    float s = 0.f, s2 = 0.f;
    #pragma unroll
    for (int i = 0; i < 6; i++) {
        v[i] = s4[lane + 32 * i];
        s  += v[i].x + v[i].y + v[i].z + v[i].w;
        s2 += v[i].x * v[i].x + v[i].y * v[i].y + v[i].z * v[i].z + v[i].w * v[i].w;
    }
    #pragma unroll
    for (int o = 16; o; o >>= 1) {
        s  += __shfl_xor_sync(0xffffffffu, s,  o);
        s2 += __shfl_xor_sync(0xffffffffu, s2, o);
    }
    float mean = s * (1.0f / DD);
    float rstd = rsqrtf(s2 * (1.0f / DD) - mean * mean + 1e-5f);

    const float4* g4 = (const float4*)g;
    const float4* b4 = (const float4*)b;
    uint2* out = (uint2*)(h_scratch + outOff + row * DD);
    #pragma unroll
    for (int i = 0; i < 6; i++) {
        float4 gg = g4[lane + 32 * i];
        float4 bb = b4[lane + 32 * i];
        float o0 = (v[i].x - mean) * rstd * gg.x + bb.x;
        float o1 = (v[i].y - mean) * rstd * gg.y + bb.y;
        float o2 = (v[i].z - mean) * rstd * gg.z + bb.z;
        float o3 = (v[i].w - mean) * rstd * gg.w + bb.w;
        uint2 p;
        p.x = pack2h(o0, o1);
        p.y = pack2h(o2, o3);
        out[lane + 32 * i] = p;
    }
}

// ---------------- fp16 tensor-core GEMM (3-stage pipeline, BK=64) ----------------
// A: [M,K] K-major fp16.  B: [N,K] K-major fp16.
// MODE 0: fp32 out (+bias).  MODE 1: QKV scatter (+bias, Q scaled).  MODE 3: gelu -> f fp16
template<int BM, int BN, int BK, int WM, int WN, int MODE>
__global__ void __launch_bounds__(256, 2)
mma_gemm(const __half* __restrict__ A, const __half* __restrict__ B,
         const float* __restrict__ bias, float* __restrict__ Cf,
         int M, int N, int K, int lda, int ldb, int ldc) {
    constexpr int BKP = BK + 8;
    constexpr int WTM = BM / WM, WTN = BN / WN;
    constexpr int MF = WTM / 16, NF = WTN / 8;
    constexpr int STAGE = (BM + BN) * BKP;     // halfs per stage

    extern __shared__ __half smem[];
    const int tid = threadIdx.x, lane = tid & 31, warp = tid >> 5;
    const int wm = warp % WM, wn = warp / WM;
    const int m0 = blockIdx.y * BM, n0 = blockIdx.x * BN;

    uint32_t sbase = (uint32_t)__cvta_generic_to_shared(smem);

    auto load_stage = [&](int s, int k0) {
        uint32_t base = sbase + (uint32_t)(s * STAGE) * 2;
        #pragma unroll 2
        for (int i = tid; i < BM * (BK / 8); i += 256) {
            int row = i / (BK / 8), c = i % (BK / 8);
            cpasync16(base + (uint32_t)(row * BKP + c * 8) * 2,
                      A + (long)(m0 + row) * lda + k0 + c * 8);
        }
        #pragma unroll 2
        for (int i = tid; i < BN * (BK / 8); i += 256) {
            int row = i / (BK / 8), c = i % (BK / 8);
            cpasync16(base + (uint32_t)(BM * BKP + row * BKP + c * 8) * 2,
                      B + (long)(n0 + row) * ldb + k0 + c * 8);
        }
    };

    float acc[MF][NF][4];
    #pragma unroll
    for (int i = 0; i < MF; i++)
        #pragma unroll
        for (int j = 0; j < NF; j++)
            #pragma unroll
            for (int q = 0; q < 4; q++) acc[i][j][q] = 0.f;

    const int nIter = K / BK;
    load_stage(0, 0); cp_commit();
    load_stage(1, BK); cp_commit();

    int s = 0;
    for (int it = 0; it < nIter; ++it) {
        if (it + 1 < nIter) cp_wait<1>(); else cp_wait<0>();
        __syncthreads();
        if (it + 2 < nIter) {
            int s2 = s + 2; if (s2 >= 3) s2 -= 3;
            load_stage(s2, (it + 2) * BK);
            cp_commit();
        }

        uint32_t base = sbase + (uint32_t)(s * STAGE) * 2;
        #pragma unroll
        for (int kk = 0; kk < BK; kk += 16) {
            uint32_t af[MF][4], bf[NF][2];
            #pragma unroll
            for (int mf = 0; mf < MF; mf++) {
                int r = wm * WTM + mf * 16 + (lane & 15);
                ldm_x4(af[mf], base + (uint32_t)(r * BKP + kk + (lane >> 4) * 8) * 2);
            }
            #pragma unroll
            for (int nf2 = 0; nf2 < NF / 2; nf2++) {
                int r = wn * WTN + nf2 * 16 + (lane & 15);
                uint32_t t[4];
                ldm_x4(t, base + (uint32_t)(BM * BKP + r * BKP + kk + (lane >> 4) * 8) * 2);
                bf[2 * nf2][0] = t[0]; bf[2 * nf2][1] = t[2];
                bf[2 * nf2 + 1][0] = t[1]; bf[2 * nf2 + 1][1] = t[3];
            }
            #pragma unroll
            for (int mf = 0; mf < MF; mf++)
                #pragma unroll
                for (int nf = 0; nf < NF; nf++)
                    mma16816(acc[mf][nf], af[mf], bf[nf]);
        }
        if (++s >= 3) s -= 3;
    }

    const int tg = lane >> 2, tp = lane & 3;
    #pragma unroll
    for (int mf = 0; mf < MF; mf++) {
        #pragma unroll
        for (int nf = 0; nf < NF; nf++) {
            int mA = m0 + wm * WTM + mf * 16 + tg;
            int nA = n0 + wn * WTN + nf * 8 + tp * 2;
            float v0 = acc[mf][nf][0], v1 = acc[mf][nf][1];
            float v2 = acc[mf][nf][2], v3 = acc[mf][nf][3];
            if (bias) {
                float b0 = bias[nA], b1 = bias[nA + 1];
                v0 += b0; v1 += b1; v2 += b0; v3 += b1;
            }
            if (MODE == 0) {
                *(float2*)&Cf[(long)mA * ldc + nA] = make_float2(v0, v1);
                *(float2*)&Cf[(long)(mA + 8) * ldc + nA] = make_float2(v2, v3);
            } else if (MODE == 1) {
                int which = nA / DD;
                int r = nA - which * DD;
                int h = r >> 6, e = r & 63;
                if (which == 2) {
                    // V transposed: strided scalar stores
                    #pragma unroll
                    for (int q = 0; q < 4; q++) {
                        int m = mA + (q >> 1) * 8;
                        int eq = e + (q & 1);
                        float v = (q == 0) ? v0 : (q == 1) ? v1 : (q == 2) ? v2 : v3;
                        int bh = (m >> 11) * HH + h;
                        h_scratch[HO_V + ((long)bh * HDIM + eq) * SS + (m & 2047)] =
                            __float2half(v);
                    }
                } else {
                    float scl = (which == 0) ? SCALEQ : 1.0f;
                    long off = (which == 0) ? HO_Q : HO_K;
                    int bh0 = (mA >> 11) * HH + h;
                    long i0 = ((long)bh0 * SS + (mA & 2047)) * HDIM + e;
                    *(uint32_t*)&h_scratch[off + i0] = pack2h(v0 * scl, v1 * scl);
                    int m8 = mA + 8;
                    int bh1 = (m8 >> 11) * HH + h;
                    long i1 = ((long)bh1 * SS + (m8 & 2047)) * HDIM + e;
                    *(uint32_t*)&h_scratch[off + i1] = pack2h(v2 * scl, v3 * scl);
                }
            } else { // MODE 3: gelu -> f (packed u32 stores)
                *(uint32_t*)&h_scratch[HO_F + (long)mA * FF + nA] =
                    pack2h(gelu_exact(v0), gelu_exact(v1));
                *(uint32_t*)&h_scratch[HO_F + (long)(mA + 8) * FF + nA] =
                    pack2h(gelu_exact(v2), gelu_exact(v3));
            }
        }
    }
}

// ---------------- flash attention (fp16, BM=64, 4 warps, 3 CTAs/SM) ----------------
#define KSTR 72
#define VSTR 136
#define KBYTES (128 * KSTR * 2)           // 18432
#define VBYTES (64 * VSTR * 2)            // 17408
#define FA_STAGE (KBYTES + VBYTES)        // 35840
#define FA_SMEM  (2 * FA_STAGE)           // 71680

__global__ void __launch_bounds__(128, 3)
flash_attn() {
    extern __shared__ char fsm[];
    uint32_t sbase = (uint32_t)__cvta_generic_to_shared(fsm);
    const int tid = threadIdx.x, lane = tid & 31, warp = tid >> 5;   // warp 0..3
    const int tg = lane >> 2, tp = lane & 3;
    const int m0 = blockIdx.x * 64;
    const int bh = blockIdx.y;

    const __half* Q = h_scratch + HO_Q;
    const __half* Kp = h_scratch + HO_K;
    const __half* Vp = h_scratch + HO_V;

    auto load_stage = [&](int s, int kk0) {
        uint32_t base = sbase + (uint32_t)(s * FA_STAGE);
        for (int i = tid; i < 128 * 8; i += 128) {
            int row = i >> 3, c = i & 7;
            cpasync16(base + (uint32_t)(row * KSTR + c * 8) * 2,
                      Kp + ((long)bh * SS + kk0 + row) * 64 + c * 8);
        }
        for (int i = tid; i < 64 * 16; i += 128) {
            int row = i >> 4, c = i & 15;
            cpasync16(base + (uint32_t)KBYTES + (uint32_t)(row * VSTR + c * 8) * 2,
                      Vp + ((long)bh * HDIM + row) * SS + kk0 + c * 8);
        }
    };

    load_stage(0, 0);
    cp_commit();

    // Q fragments (layout-exact register loads) — overlap with stage-0 cp.async
    uint32_t qf[4][4];
    {
        long r0 = (long)bh * SS + m0 + warp * 16 + tg;
        #pragma unroll
        for (int ks = 0; ks < 4; ks++) {
            int c0 = ks * 16 + tp * 2;
            qf[ks][0] = *(const uint32_t*)&Q[r0 * 64 + c0];
            qf[ks][1] = *(const uint32_t*)&Q[(r0 + 8) * 64 + c0];
            qf[ks][2] = *(const uint32_t*)&Q[r0 * 64 + c0 + 8];
            qf[ks][3] = *(const uint32_t*)&Q[(r0 + 8) * 64 + c0 + 8];
        }
    }

    float Oacc[8][4];
    #pragma unroll
    for (int i = 0; i < 8; i++)
        #pragma unroll
        for (int q = 0; q < 4; q++) Oacc[i][q] = 0.f;
    float mrun[2] = { -1e30f, -1e30f };
    float lrun[2] = { 0.f, 0.f };

    for (int it = 0; it < 16; ++it) {
        int s = it & 1;
        if (it + 1 < 16) {
            load_stage(s ^ 1, (it + 1) * 128);
            cp_commit();
            cp_wait<1>();
        } else {
            cp_wait<0>();
        }
        __syncthreads();

        uint32_t base = sbase + (uint32_t)(s * FA_STAGE);

        // ---- S = Q K^T (scale folded in Q) ----
        float sc[16][4];
        #pragma unroll
        for (int i = 0; i < 16; i++)
            #pragma unroll
            for (int q = 0; q < 4; q++) sc[i][q] = 0.f;

        #pragma unroll
        for (int ks = 0; ks < 4; ks++) {
            #pragma unroll
            for (int nf2 = 0; nf2 < 8; nf2++) {
                int r = nf2 * 16 + (lane & 15);
                uint32_t t[4], b0[2], b1[2];
                ldm_x4(t, base + (uint32_t)(r * KSTR + ks * 16 + (lane >> 4) * 8) * 2);
                b0[0] = t[0]; b0[1] = t[2];
                b1[0] = t[1]; b1[1] = t[3];
                mma16816(sc[2 * nf2],     qf[ks], b0);
                mma16816(sc[2 * nf2 + 1], qf[ks], b1);
            }
        }

        // ---- online softmax (exp2 domain, raw MUFU) ----
        float mx0 = mrun[0], mx1 = mrun[1];
        #pragma unroll
        for (int nf = 0; nf < 16; nf++) {
            mx0 = fmaxf(mx0, fmaxf(sc[nf][0], sc[nf][1]));
            mx1 = fmaxf(mx1, fmaxf(sc[nf][2], sc[nf][3]));
        }
        mx0 = fmaxf(mx0, __shfl_xor_sync(0xffffffffu, mx0, 1));
        mx0 = fmaxf(mx0, __shfl_xor_sync(0xffffffffu, mx0, 2));
        mx1 = fmaxf(mx1, __shfl_xor_sync(0xffffffffu, mx1, 1));
        mx1 = fmaxf(mx1, __shfl_xor_sync(0xffffffffu, mx1, 2));

        float alpha0 = ex2(mrun[0] - mx0);
        float alpha1 = ex2(mrun[1] - mx1);
        mrun[0] = mx0; mrun[1] = mx1;

        float sum0 = 0.f, sum1 = 0.f;
        #pragma unroll
        for (int nf = 0; nf < 16; nf++) {
            sc[nf][0] = ex2(sc[nf][0] - mx0);
            sc[nf][1] = ex2(sc[nf][1] - mx0);
            sc[nf][2] = ex2(sc[nf][2] - mx1);
            sc[nf][3] = ex2(sc[nf][3] - mx1);
            sum0 += sc[nf][0] + sc[nf][1];
            sum1 += sc[nf][2] + sc[nf][3];
        }
        sum0 += __shfl_xor_sync(0xffffffffu, sum0, 1);
        sum0 += __shfl_xor_sync(0xffffffffu, sum0, 2);
        sum1 += __shfl_xor_sync(0xffffffffu, sum1, 1);
        sum1 += __shfl_xor_sync(0xffffffffu, sum1, 2);
        lrun[0] = lrun[0] * alpha0 + sum0;
        lrun[1] = lrun[1] * alpha1 + sum1;

        #pragma unroll
        for (int nf = 0; nf < 8; nf++) {
            Oacc[nf][0] *= alpha0; Oacc[nf][1] *= alpha0;
            Oacc[nf][2] *= alpha1; Oacc[nf][3] *= alpha1;
        }

        // ---- O += P V ----
        #pragma unroll
        for (int ks = 0; ks < 8; ks++) {
            int u = 2 * ks, vt = 2 * ks + 1;
            uint32_t af[4];
            af[0] = pack2h(sc[u][0],  sc[u][1]);
            af[1] = pack2h(sc[u][2],  sc[u][3]);
            af[2] = pack2h(sc[vt][0], sc[vt][1]);
            af[3] = pack2h(sc[vt][2], sc[vt][3]);
            #pragma unroll
            for (int nf2 = 0; nf2 < 4; nf2++) {
                int r = nf2 * 16 + (lane & 15);
                uint32_t t[4], b0[2], b1[2];
                ldm_x4(t, base + (uint32_t)KBYTES
                           + (uint32_t)(r * VSTR + ks * 16 + (lane >> 4) * 8) * 2);
                b0[0] = t[0]; b0[1] = t[2];
                b1[0] = t[1]; b1[1] = t[3];
                mma16816(Oacc[2 * nf2],     af, b0);
                mma16816(Oacc[2 * nf2 + 1], af, b1);
            }
        }
        __syncthreads();
    }

    // ---- epilogue ----
    float inv0 = 1.0f / lrun[0], inv1 = 1.0f / lrun[1];
    int b = bh / HH, h = bh % HH;
    long tok0 = (long)b * SS + m0 + warp * 16 + tg;
    __half* O = h_scratch + HO_OC;
    #pragma unroll
    for (int nf = 0; nf < 8; nf++) {
        int col = h * HDIM + nf * 8 + tp * 2;
        *(uint32_t*)&O[tok0 * DD + col] =
            pack2h(Oacc[nf][0] * inv0, Oacc[nf][1] * inv0);
        *(uint32_t*)&O[(tok0 + 8) * DD + col] =
            pack2h(Oacc[nf][2] * inv1, Oacc[nf][3] * inv1);
    }
}

// ---------------- launch ----------------
extern "C" void kernel_launch(void* const* d_in, const int* in_sizes, int n_in,
                              void* d_out, int out_size) {
    const float* x   = (const float*)d_in[0];
    const float* Wq  = (const float*)d_in[1];
    const float* bq  = (const float*)d_in[2];
    const float* Wk  = (const float*)d_in[3];
    const float* bk  = (const float*)d_in[4];
    const float* Wv  = (const float*)d_in[5];
    const float* bv  = (const float*)d_in[6];
    const float* Wo  = (const float*)d_in[7];
    const float* bo  = (const float*)d_in[8];
    const float* W1  = (const float*)d_in[9];
    const float* b1  = (const float*)d_in[10];
    const float* W2  = (const float*)d_in[11];
    const float* b2  = (const float*)d_in[12];
    const float* g1  = (const float*)d_in[13];
    const float* be1 = (const float*)d_in[14];
    const float* g2  = (const float*)d_in[15];
    const float* be2 = (const float*)d_in[16];
    float* out = (float*)d_out;

    static __half* hs = nullptr;
    static float* fs = nullptr;
    if (!hs) {
        void* p;
        cudaGetSymbolAddress(&p, h_scratch); hs = (__half*)p;
        cudaGetSymbolAddress(&p, f_scratch); fs = (float*)p;
    }

    const int SMEM_BIG = 3 * ((128 + 128) * 72) * 2;   // 110592 B (BK=64, 3 stages)
    const int SMEM_64  = 3 * ((128 + 64) * 72) * 2;    // 82944 B
    static bool attrDone = false;
    if (!attrDone) {
        cudaFuncSetAttribute((const void*)mma_gemm<128,128,64,2,4,1>,
                             cudaFuncAttributeMaxDynamicSharedMemorySize, SMEM_BIG);
        cudaFuncSetAttribute((const void*)mma_gemm<128,128,64,2,4,3>,
                             cudaFuncAttributeMaxDynamicSharedMemorySize, SMEM_BIG);
        cudaFuncSetAttribute((const void*)mma_gemm<128,64,64,4,2,0>,
                             cudaFuncAttributeMaxDynamicSharedMemorySize, SMEM_64);
        cudaFuncSetAttribute((const void*)flash_attn,
                             cudaFuncAttributeMaxDynamicSharedMemorySize, FA_SMEM);
        attrDone = true;
    }

    // 1) weight/bias packing + conversion
    pack_wqkv<<<(unsigned)((2304L * 768 + 255) / 256), 256>>>(Wq, Wk, Wv, bq, bk, bv);
    transpose3<<<5184, dim3(32, 8)>>>(Wo, W1, W2);

    // 2) LN1 -> h (fp16)
    ln_fp16<<<NTOK / 8, 256>>>(x, 0, g1, be1, HO_H);

    // 3) QKV GEMM with scatter epilogue (Q pre-scaled by 0.125*log2e)
    mma_gemm<128,128,64,2,4,1><<<dim3(18, 64), 256, SMEM_BIG>>>(
        hs + HO_H, hs + HO_WQKV, fs + FO_BQKV, nullptr,
        NTOK, 3 * DD, DD, DD, DD, 0);

    // 4) fused flash attention -> Oc (BM=64, 3 CTAs/SM)
    flash_attn<<<dim3(32, BH), 128, FA_SMEM>>>();

    // 5) O-proj -> a (fp32)
    mma_gemm<128,64,64,4,2,0><<<dim3(12, 64), 256, SMEM_64>>>(
        hs + HO_OC, hs + HO_WO, bo, fs + FO_A,
        NTOK, DD, DD, DD, DD, DD);

    // 6) LN2 -> h2 (fp16)
    ln_fp16<<<NTOK / 8, 256>>>(nullptr, 1, g2, be2, HO_H2);

    // 7) MLP1 + GELU -> f (fp16)
    mma_gemm<128,128,64,2,4,3><<<dim3(24, 64), 256, SMEM_BIG>>>(
        hs + HO_H2, hs + HO_W1, b1, nullptr,
        NTOK, FF, DD, DD, DD, 0);

    // 8) MLP2 -> out (fp32)
    mma_gemm<128,64,64,4,2,0><<<dim3(12, 64), 256, SMEM_64>>>(
        hs + HO_F, hs + HO_W2, b2, out,
        NTOK, DD, FF, FF, FF, DD);
}